// round 1
// baseline (speedup 1.0000x reference)
#include <cuda_runtime.h>
#include <math.h>

// ---------------------------------------------------------------------------
// Problem constants
// ---------------------------------------------------------------------------
#define BATCH   2
#define SEQ     2048
#define HID     1024
#define HEADS   16
#define HDIM    64
#define ROWS    (BATCH * SEQ)          // 4096

// ---------------------------------------------------------------------------
// Scratch (static device globals -- no runtime allocation)
// ---------------------------------------------------------------------------
__device__ float g_Q[ROWS * HID];
__device__ float g_K[ROWS * HID];
__device__ float g_V[ROWS * HID];
__device__ float g_CTX[ROWS * HID];
__device__ float g_X[ROWS * HID];

// ---------------------------------------------------------------------------
// SGEMM: C[M,N] = A[M,K] @ W[K,N] + bias[N] (+ residual[M,N])
// 128x128 block tile, BK=8, 256 threads, 8x8 register tile per thread.
// ---------------------------------------------------------------------------
#define BM 128
#define BN 128
#define BK 8

__global__ __launch_bounds__(256)
void sgemm_bias(const float* __restrict__ A, const float* __restrict__ W,
                const float* __restrict__ bias, const float* __restrict__ res,
                float* __restrict__ C, int M, int N, int K)
{
    __shared__ float As[BK][BM];
    __shared__ float Bs[BK][BN];

    const int tid = threadIdx.x;
    const int bm = blockIdx.y * BM;
    const int bn = blockIdx.x * BN;

    const int tx = tid & 15;       // 0..15 -> cols tx*8
    const int ty = tid >> 4;       // 0..15 -> rows ty*8

    const int arow  = tid >> 1;          // 0..127
    const int acol4 = (tid & 1) * 4;     // 0 or 4
    const int brow  = tid >> 5;          // 0..7
    const int bcol4 = (tid & 31) * 4;    // 0..124

    float acc[8][8];
#pragma unroll
    for (int i = 0; i < 8; i++)
#pragma unroll
        for (int j = 0; j < 8; j++) acc[i][j] = 0.f;

    for (int k0 = 0; k0 < K; k0 += BK) {
        float4 av = *(const float4*)&A[(size_t)(bm + arow) * K + k0 + acol4];
        As[acol4 + 0][arow] = av.x;
        As[acol4 + 1][arow] = av.y;
        As[acol4 + 2][arow] = av.z;
        As[acol4 + 3][arow] = av.w;
        float4 bv = *(const float4*)&W[(size_t)(k0 + brow) * N + bn + bcol4];
        *(float4*)&Bs[brow][bcol4] = bv;
        __syncthreads();

#pragma unroll
        for (int kk = 0; kk < BK; kk++) {
            float4 a0 = *(float4*)&As[kk][ty * 8];
            float4 a1 = *(float4*)&As[kk][ty * 8 + 4];
            float4 b0 = *(float4*)&Bs[kk][tx * 8];
            float4 b1 = *(float4*)&Bs[kk][tx * 8 + 4];
            float a[8] = {a0.x, a0.y, a0.z, a0.w, a1.x, a1.y, a1.z, a1.w};
            float b[8] = {b0.x, b0.y, b0.z, b0.w, b1.x, b1.y, b1.z, b1.w};
#pragma unroll
            for (int i = 0; i < 8; i++)
#pragma unroll
                for (int j = 0; j < 8; j++) acc[i][j] += a[i] * b[j];
        }
        __syncthreads();
    }

#pragma unroll
    for (int i = 0; i < 8; i++) {
        const int row = bm + ty * 8 + i;
#pragma unroll
        for (int j = 0; j < 8; j += 4) {
            const int col = bn + tx * 8 + j;
            float4 o;
            o.x = acc[i][j + 0] + bias[col + 0];
            o.y = acc[i][j + 1] + bias[col + 1];
            o.z = acc[i][j + 2] + bias[col + 2];
            o.w = acc[i][j + 3] + bias[col + 3];
            if (res) {
                float4 r = *(const float4*)&res[(size_t)row * N + col];
                o.x += r.x; o.y += r.y; o.z += r.z; o.w += r.w;
            }
            *(float4*)&C[(size_t)row * N + col] = o;
        }
    }
}

// ---------------------------------------------------------------------------
// Flash attention (fp32): per block one (q-tile=64, head, batch).
// Online softmax over 32 K-tiles of 64. V kept transposed in smem so that
// both S=QK^T and O+=P V are row(float4)-dot-row(float4) over smem.
// ---------------------------------------------------------------------------
#define BQ   64
#define BKT  64
#define SSTR 68          // padded row stride (floats), keeps float4 alignment

#define ATT_SMEM_FLOATS (4 * 64 * SSTR + 3 * 64)
#define ATT_SMEM_BYTES  (ATT_SMEM_FLOATS * 4)

__global__ __launch_bounds__(256)
void flash_attn(const float* __restrict__ Q, const float* __restrict__ K,
                const float* __restrict__ V, float* __restrict__ Ctx)
{
    extern __shared__ float sm[];
    float* Qs  = sm;                       // [64][SSTR]
    float* Ks  = Qs  + 64 * SSTR;          // [64][SSTR]
    float* Vts = Ks  + 64 * SSTR;          // [64][SSTR]  (transposed: [d][k])
    float* Ss  = Vts + 64 * SSTR;          // [64][SSTR]
    float* m_s = Ss  + 64 * SSTR;          // [64]
    float* l_s = m_s + 64;                 // [64]
    float* a_s = l_s + 64;                 // [64]

    const int tid = threadIdx.x;
    const int q0  = blockIdx.x * BQ;
    const int h   = blockIdx.y;
    const int b   = blockIdx.z;
    const size_t base = (size_t)b * SEQ * HID + (size_t)h * HDIM;

    // Load Q tile
#pragma unroll
    for (int t = 0; t < 4; t++) {
        int fi  = tid + t * 256;           // 0..1023
        int row = fi >> 4;
        int d4  = (fi & 15) * 4;
        float4 v = *(const float4*)&Q[base + (size_t)(q0 + row) * HID + d4];
        *(float4*)&Qs[row * SSTR + d4] = v;
    }
    if (tid < 64) { m_s[tid] = -1e30f; l_s[tid] = 0.f; }

    const int tx = tid & 15;
    const int ty = tid >> 4;
    const float scale = 0.125f;            // 1/sqrt(64)

    float acc[4][4];
#pragma unroll
    for (int i = 0; i < 4; i++)
#pragma unroll
        for (int j = 0; j < 4; j++) acc[i][j] = 0.f;

    for (int kt = 0; kt < SEQ / BKT; kt++) {
        const int k0 = kt * BKT;
        __syncthreads();   // protects Ks/Vts/Ss reuse + initial Q/m/l visibility

        // Load K tile + V tile (transposed)
#pragma unroll
        for (int t = 0; t < 4; t++) {
            int fi  = tid + t * 256;
            int row = fi >> 4;
            int d4  = (fi & 15) * 4;
            float4 kv = *(const float4*)&K[base + (size_t)(k0 + row) * HID + d4];
            *(float4*)&Ks[row * SSTR + d4] = kv;
            float4 vv = *(const float4*)&V[base + (size_t)(k0 + row) * HID + d4];
            Vts[(d4 + 0) * SSTR + row] = vv.x;
            Vts[(d4 + 1) * SSTR + row] = vv.y;
            Vts[(d4 + 2) * SSTR + row] = vv.z;
            Vts[(d4 + 3) * SSTR + row] = vv.w;
        }
        __syncthreads();

        // S = Q @ K^T * scale
        float s[4][4];
#pragma unroll
        for (int i = 0; i < 4; i++)
#pragma unroll
            for (int j = 0; j < 4; j++) s[i][j] = 0.f;

#pragma unroll
        for (int d4 = 0; d4 < 16; d4++) {
            float4 q[4], k[4];
#pragma unroll
            for (int i = 0; i < 4; i++) q[i] = *(float4*)&Qs[(ty * 4 + i) * SSTR + d4 * 4];
#pragma unroll
            for (int j = 0; j < 4; j++) k[j] = *(float4*)&Ks[(tx * 4 + j) * SSTR + d4 * 4];
#pragma unroll
            for (int i = 0; i < 4; i++)
#pragma unroll
                for (int j = 0; j < 4; j++)
                    s[i][j] += q[i].x * k[j].x + q[i].y * k[j].y +
                               q[i].z * k[j].z + q[i].w * k[j].w;
        }
#pragma unroll
        for (int i = 0; i < 4; i++)
#pragma unroll
            for (int j = 0; j < 4; j++)
                Ss[(ty * 4 + i) * SSTR + tx * 4 + j] = s[i][j] * scale;
        __syncthreads();

        // Online softmax (4 threads per row, 16 cols each)
        {
            const int r  = tid >> 2;
            const int qq = tid & 3;
            const int c0 = qq * 16;
            float mx = -1e30f;
#pragma unroll
            for (int c = 0; c < 16; c++) mx = fmaxf(mx, Ss[r * SSTR + c0 + c]);
            mx = fmaxf(mx, __shfl_xor_sync(0xffffffffu, mx, 1));
            mx = fmaxf(mx, __shfl_xor_sync(0xffffffffu, mx, 2));
            float m_old = m_s[r];
            float m_new = fmaxf(m_old, mx);
            float sum = 0.f;
#pragma unroll
            for (int c = 0; c < 16; c++) {
                float p = __expf(Ss[r * SSTR + c0 + c] - m_new);
                Ss[r * SSTR + c0 + c] = p;
                sum += p;
            }
            sum += __shfl_xor_sync(0xffffffffu, sum, 1);
            sum += __shfl_xor_sync(0xffffffffu, sum, 2);
            if (qq == 0) {
                float al = __expf(m_old - m_new);
                a_s[r] = al;
                l_s[r] = l_s[r] * al + sum;
                m_s[r] = m_new;
            }
        }
        __syncthreads();

        // O = O*alpha + P @ V   (Vts is [d][k], so this is row-dot-row too)
        float al[4];
#pragma unroll
        for (int i = 0; i < 4; i++) al[i] = a_s[ty * 4 + i];
#pragma unroll
        for (int i = 0; i < 4; i++)
#pragma unroll
            for (int j = 0; j < 4; j++) acc[i][j] *= al[i];

#pragma unroll
        for (int k4 = 0; k4 < 16; k4++) {
            float4 p[4], v[4];
#pragma unroll
            for (int i = 0; i < 4; i++) p[i] = *(float4*)&Ss[(ty * 4 + i) * SSTR + k4 * 4];
#pragma unroll
            for (int j = 0; j < 4; j++) v[j] = *(float4*)&Vts[(tx * 4 + j) * SSTR + k4 * 4];
#pragma unroll
            for (int i = 0; i < 4; i++)
#pragma unroll
                for (int j = 0; j < 4; j++)
                    acc[i][j] += p[i].x * v[j].x + p[i].y * v[j].y +
                                 p[i].z * v[j].z + p[i].w * v[j].w;
        }
    }

    // Write normalized context (l_s final; last softmax wrote it before the
    // preceding __syncthreads of the final O-update phase)
#pragma unroll
    for (int i = 0; i < 4; i++) {
        const int ri = ty * 4 + i;
        const float inv_l = 1.f / l_s[ri];
        float4 o;
        o.x = acc[i][0] * inv_l;
        o.y = acc[i][1] * inv_l;
        o.z = acc[i][2] * inv_l;
        o.w = acc[i][3] * inv_l;
        *(float4*)&Ctx[base + (size_t)(q0 + ri) * HID + tx * 4] = o;
    }
}

// ---------------------------------------------------------------------------
// LayerNorm: one block per row of 1024
// ---------------------------------------------------------------------------
__global__ __launch_bounds__(256)
void layernorm_kernel(const float* __restrict__ X, const float* __restrict__ gamma,
                      const float* __restrict__ beta, float* __restrict__ out)
{
    __shared__ float red[2][8];
    const int row = blockIdx.x;
    const int tid = threadIdx.x;
    const float* x = X + (size_t)row * HID;

    float4 v = *(const float4*)&x[tid * 4];
    float s  = v.x + v.y + v.z + v.w;
    float ss = v.x * v.x + v.y * v.y + v.z * v.z + v.w * v.w;
#pragma unroll
    for (int o = 16; o > 0; o >>= 1) {
        s  += __shfl_xor_sync(0xffffffffu, s, o);
        ss += __shfl_xor_sync(0xffffffffu, ss, o);
    }
    const int w = tid >> 5, l = tid & 31;
    if (l == 0) { red[0][w] = s; red[1][w] = ss; }
    __syncthreads();
    if (w == 0) {
        float s2  = (l < 8) ? red[0][l] : 0.f;
        float ss2 = (l < 8) ? red[1][l] : 0.f;
#pragma unroll
        for (int o = 4; o > 0; o >>= 1) {
            s2  += __shfl_xor_sync(0xffffffffu, s2, o);
            ss2 += __shfl_xor_sync(0xffffffffu, ss2, o);
        }
        if (l == 0) { red[0][0] = s2; red[1][0] = ss2; }
    }
    __syncthreads();

    const float mean = red[0][0] * (1.f / HID);
    const float var  = red[1][0] * (1.f / HID) - mean * mean;
    const float rstd = rsqrtf(var + 1e-5f);

    const int c = tid * 4;
    float4 gv = *(const float4*)&gamma[c];
    float4 bv = *(const float4*)&beta[c];
    float4 o;
    o.x = (v.x - mean) * rstd * gv.x + bv.x;
    o.y = (v.y - mean) * rstd * gv.y + bv.y;
    o.z = (v.z - mean) * rstd * gv.z + bv.z;
    o.w = (v.w - mean) * rstd * gv.w + bv.w;
    *(float4*)&out[(size_t)row * HID + c] = o;
}

// ---------------------------------------------------------------------------
// Launch
// ---------------------------------------------------------------------------
extern "C" void kernel_launch(void* const* d_in, const int* in_sizes, int n_in,
                              void* d_out, int out_size)
{
    const float* hidden = (const float*)d_in[0];
    const float* Wq = (const float*)d_in[1];
    const float* bq = (const float*)d_in[2];
    const float* Wk = (const float*)d_in[3];
    const float* bk = (const float*)d_in[4];
    const float* Wv = (const float*)d_in[5];
    const float* bv = (const float*)d_in[6];
    const float* Wo = (const float*)d_in[7];
    const float* bo = (const float*)d_in[8];
    const float* gamma = (const float*)d_in[9];
    const float* beta  = (const float*)d_in[10];
    float* out = (float*)d_out;

    float *q, *k, *v, *ctx, *x;
    cudaGetSymbolAddress((void**)&q,   g_Q);
    cudaGetSymbolAddress((void**)&k,   g_K);
    cudaGetSymbolAddress((void**)&v,   g_V);
    cudaGetSymbolAddress((void**)&ctx, g_CTX);
    cudaGetSymbolAddress((void**)&x,   g_X);

    dim3 gg(HID / BN, ROWS / BM);   // (8, 32)
    dim3 bb(256);

    sgemm_bias<<<gg, bb>>>(hidden, Wq, bq, nullptr, q, ROWS, HID, HID);
    sgemm_bias<<<gg, bb>>>(hidden, Wk, bk, nullptr, k, ROWS, HID, HID);
    sgemm_bias<<<gg, bb>>>(hidden, Wv, bv, nullptr, v, ROWS, HID, HID);

    cudaFuncSetAttribute(flash_attn, cudaFuncAttributeMaxDynamicSharedMemorySize,
                         ATT_SMEM_BYTES);
    flash_attn<<<dim3(SEQ / BQ, HEADS, BATCH), 256, ATT_SMEM_BYTES>>>(q, k, v, ctx);

    sgemm_bias<<<gg, bb>>>(ctx, Wo, bo, hidden, x, ROWS, HID, HID);

    layernorm_kernel<<<ROWS, 256>>>(x, gamma, beta, out);
}

// round 2
// speedup vs baseline: 2.9067x; 2.9067x over previous
#include <cuda_runtime.h>
#include <math.h>

// ---------------------------------------------------------------------------
// Problem constants
// ---------------------------------------------------------------------------
#define BATCH   2
#define SEQ     2048
#define HID     1024
#define HEADS   16
#define HDIM    64
#define ROWS    (BATCH * SEQ)          // 4096

// ---------------------------------------------------------------------------
// Scratch (static device globals -- no runtime allocation)
// ---------------------------------------------------------------------------
__device__ float g_Q[ROWS * HID];
__device__ float g_K[ROWS * HID];
__device__ float g_V[ROWS * HID];
__device__ float g_CTX[ROWS * HID];
__device__ float g_X[ROWS * HID];

// ---------------------------------------------------------------------------
// SGEMM: C[M,N] = A[M,K] @ W[K,N] + bias[N] (+ residual[M,N])
// 128x128 block tile, BK=8, 256 threads, 8x8 register tile per thread.
// ---------------------------------------------------------------------------
#define BM 128
#define BN 128
#define BK 8

__global__ __launch_bounds__(256)
void sgemm_bias(const float* __restrict__ A, const float* __restrict__ W,
                const float* __restrict__ bias, const float* __restrict__ res,
                float* __restrict__ C, int M, int N, int K)
{
    __shared__ float As[BK][BM];
    __shared__ float Bs[BK][BN];

    const int tid = threadIdx.x;
    const int bm = blockIdx.y * BM;
    const int bn = blockIdx.x * BN;

    const int tx = tid & 15;       // 0..15 -> cols tx*8
    const int ty = tid >> 4;       // 0..15 -> rows ty*8

    const int arow  = tid >> 1;          // 0..127
    const int acol4 = (tid & 1) * 4;     // 0 or 4
    const int brow  = tid >> 5;          // 0..7
    const int bcol4 = (tid & 31) * 4;    // 0..124

    float acc[8][8];
#pragma unroll
    for (int i = 0; i < 8; i++)
#pragma unroll
        for (int j = 0; j < 8; j++) acc[i][j] = 0.f;

    for (int k0 = 0; k0 < K; k0 += BK) {
        float4 av = *(const float4*)&A[(size_t)(bm + arow) * K + k0 + acol4];
        As[acol4 + 0][arow] = av.x;
        As[acol4 + 1][arow] = av.y;
        As[acol4 + 2][arow] = av.z;
        As[acol4 + 3][arow] = av.w;
        float4 bv = *(const float4*)&W[(size_t)(k0 + brow) * N + bn + bcol4];
        *(float4*)&Bs[brow][bcol4] = bv;
        __syncthreads();

#pragma unroll
        for (int kk = 0; kk < BK; kk++) {
            float4 a0 = *(float4*)&As[kk][ty * 8];
            float4 a1 = *(float4*)&As[kk][ty * 8 + 4];
            float4 b0 = *(float4*)&Bs[kk][tx * 8];
            float4 b1 = *(float4*)&Bs[kk][tx * 8 + 4];
            float a[8] = {a0.x, a0.y, a0.z, a0.w, a1.x, a1.y, a1.z, a1.w};
            float b[8] = {b0.x, b0.y, b0.z, b0.w, b1.x, b1.y, b1.z, b1.w};
#pragma unroll
            for (int i = 0; i < 8; i++)
#pragma unroll
                for (int j = 0; j < 8; j++) acc[i][j] += a[i] * b[j];
        }
        __syncthreads();
    }

#pragma unroll
    for (int i = 0; i < 8; i++) {
        const int row = bm + ty * 8 + i;
#pragma unroll
        for (int j = 0; j < 8; j += 4) {
            const int col = bn + tx * 8 + j;
            float4 o;
            o.x = acc[i][j + 0] + bias[col + 0];
            o.y = acc[i][j + 1] + bias[col + 1];
            o.z = acc[i][j + 2] + bias[col + 2];
            o.w = acc[i][j + 3] + bias[col + 3];
            if (res) {
                float4 r = *(const float4*)&res[(size_t)row * N + col];
                o.x += r.x; o.y += r.y; o.z += r.z; o.w += r.w;
            }
            *(float4*)&C[(size_t)row * N + col] = o;
        }
    }
}

// ---------------------------------------------------------------------------
// Flash attention v2 (fp32):
//   128 (q) x 128 (k) tiles, 256 threads, 8x8 register tile for QK^T,
//   softmax fully in registers (shfl over the 16 tx lanes),
//   8x4 register tile for P@V. Only P transits shared memory.
//
// Shared layout (d-major for Q/K so inner loop loads are conflict-free):
//   Qs [64][128]   Ks [64][128]   Vs [128][64]   Ps [128][128]   = 160 KB
//
// Thread (tx=tid&15, ty=tid>>4) owns:
//   q rows  {ty*4..+3} u {64+ty*4..+3}
//   k cols  {tx*4..+3} u {64+tx*4..+3}   (QK phase)
//   d cols  {tx*4..+3}                   (PV phase, d=64)
// ---------------------------------------------------------------------------
#define BQ   128
#define BKT  128
#define QSTR 128
#define VSTR 64
#define PSTR 128

#define ATT_SMEM_FLOATS (64*QSTR + 64*QSTR + 128*VSTR + 128*PSTR)
#define ATT_SMEM_BYTES  (ATT_SMEM_FLOATS * 4)

__global__ __launch_bounds__(256)
void flash_attn(const float* __restrict__ Q, const float* __restrict__ K,
                const float* __restrict__ V, float* __restrict__ Ctx)
{
    extern __shared__ float sm[];
    float* Qs = sm;                  // [64][QSTR]   (d-major)
    float* Ks = Qs + 64 * QSTR;      // [64][QSTR]   (d-major)
    float* Vs = Ks + 64 * QSTR;      // [128][VSTR]  (k-major)
    float* Ps = Vs + 128 * VSTR;     // [128][PSTR]  (q-major)

    const int tid = threadIdx.x;
    const int tx = tid & 15;
    const int ty = tid >> 4;
    const int q0 = blockIdx.x * BQ;
    const int h  = blockIdx.y;
    const int b  = blockIdx.z;
    const size_t base = (size_t)b * SEQ * HID + (size_t)h * HDIM;

    // ---- load Q tile transposed into Qs[d][q] ----
#pragma unroll
    for (int t = 0; t < 8; t++) {
        int fi  = tid + t * 256;           // 0..2047
        int row = fi & 127;
        int d4  = (fi >> 7) * 4;
        float4 v = *(const float4*)&Q[base + (size_t)(q0 + row) * HID + d4];
        Qs[(d4 + 0) * QSTR + row] = v.x;
        Qs[(d4 + 1) * QSTR + row] = v.y;
        Qs[(d4 + 2) * QSTR + row] = v.z;
        Qs[(d4 + 3) * QSTR + row] = v.w;
    }

    float m[8], l[8], acc[8][4];
#pragma unroll
    for (int i = 0; i < 8; i++) {
        m[i] = -1e30f; l[i] = 0.f;
#pragma unroll
        for (int j = 0; j < 4; j++) acc[i][j] = 0.f;
    }

    const float scale = 0.125f;        // 1/sqrt(64)

    for (int kt = 0; kt < SEQ / BKT; kt++) {
        const int k0 = kt * BKT;
        __syncthreads();               // Ks/Vs free (prev PV done); Qs visible

        // ---- load K tile transposed + V tile natural ----
#pragma unroll
        for (int t = 0; t < 8; t++) {
            int fi  = tid + t * 256;
            int row = fi & 127;
            int d4  = (fi >> 7) * 4;
            float4 kv = *(const float4*)&K[base + (size_t)(k0 + row) * HID + d4];
            Ks[(d4 + 0) * QSTR + row] = kv.x;
            Ks[(d4 + 1) * QSTR + row] = kv.y;
            Ks[(d4 + 2) * QSTR + row] = kv.z;
            Ks[(d4 + 3) * QSTR + row] = kv.w;
            int vrow = fi >> 4;
            int vd4  = (fi & 15) * 4;
            float4 vv = *(const float4*)&V[base + (size_t)(k0 + vrow) * HID + vd4];
            *(float4*)&Vs[vrow * VSTR + vd4] = vv;
        }
        __syncthreads();

        // ---- S = Q @ K^T  (8x8 register tile) ----
        float s[8][8];
#pragma unroll
        for (int i = 0; i < 8; i++)
#pragma unroll
            for (int j = 0; j < 8; j++) s[i][j] = 0.f;

#pragma unroll 4
        for (int d = 0; d < 64; d++) {
            float4 qa = *(float4*)&Qs[d * QSTR + ty * 4];
            float4 qb = *(float4*)&Qs[d * QSTR + 64 + ty * 4];
            float4 ka = *(float4*)&Ks[d * QSTR + tx * 4];
            float4 kb = *(float4*)&Ks[d * QSTR + 64 + tx * 4];
            float a[8] = {qa.x, qa.y, qa.z, qa.w, qb.x, qb.y, qb.z, qb.w};
            float bb[8] = {ka.x, ka.y, ka.z, ka.w, kb.x, kb.y, kb.z, kb.w};
#pragma unroll
            for (int i = 0; i < 8; i++)
#pragma unroll
                for (int j = 0; j < 8; j++) s[i][j] += a[i] * bb[j];
        }

        // ---- softmax in registers (row spread over 16 tx lanes) ----
#pragma unroll
        for (int i = 0; i < 8; i++) {
#pragma unroll
            for (int j = 0; j < 8; j++) s[i][j] *= scale;
            float mx = s[i][0];
#pragma unroll
            for (int j = 1; j < 8; j++) mx = fmaxf(mx, s[i][j]);
            mx = fmaxf(mx, __shfl_xor_sync(0xffffffffu, mx, 1));
            mx = fmaxf(mx, __shfl_xor_sync(0xffffffffu, mx, 2));
            mx = fmaxf(mx, __shfl_xor_sync(0xffffffffu, mx, 4));
            mx = fmaxf(mx, __shfl_xor_sync(0xffffffffu, mx, 8));
            float m_new = fmaxf(m[i], mx);
            float alpha = __expf(m[i] - m_new);
            float sum = 0.f;
#pragma unroll
            for (int j = 0; j < 8; j++) {
                s[i][j] = __expf(s[i][j] - m_new);
                sum += s[i][j];
            }
            sum += __shfl_xor_sync(0xffffffffu, sum, 1);
            sum += __shfl_xor_sync(0xffffffffu, sum, 2);
            sum += __shfl_xor_sync(0xffffffffu, sum, 4);
            sum += __shfl_xor_sync(0xffffffffu, sum, 8);
            l[i] = l[i] * alpha + sum;
            m[i] = m_new;
#pragma unroll
            for (int j = 0; j < 4; j++) acc[i][j] *= alpha;
        }

        // ---- write P to shared ([q][k], float4 conflict-free) ----
#pragma unroll
        for (int i = 0; i < 8; i++) {
            int r = (i < 4) ? (ty * 4 + i) : (60 + ty * 4 + i);
            *(float4*)&Ps[r * PSTR + tx * 4] =
                make_float4(s[i][0], s[i][1], s[i][2], s[i][3]);
            *(float4*)&Ps[r * PSTR + 64 + tx * 4] =
                make_float4(s[i][4], s[i][5], s[i][6], s[i][7]);
        }
        __syncthreads();

        // ---- O += P @ V  (8 rows x 4 d per thread) ----
#pragma unroll 4
        for (int k4 = 0; k4 < 32; k4++) {
            float4 v0 = *(float4*)&Vs[(k4 * 4 + 0) * VSTR + tx * 4];
            float4 v1 = *(float4*)&Vs[(k4 * 4 + 1) * VSTR + tx * 4];
            float4 v2 = *(float4*)&Vs[(k4 * 4 + 2) * VSTR + tx * 4];
            float4 v3 = *(float4*)&Vs[(k4 * 4 + 3) * VSTR + tx * 4];
#pragma unroll
            for (int i = 0; i < 8; i++) {
                int r = (i < 4) ? (ty * 4 + i) : (60 + ty * 4 + i);
                float4 p = *(float4*)&Ps[r * PSTR + k4 * 4];
                acc[i][0] += p.x * v0.x + p.y * v1.x + p.z * v2.x + p.w * v3.x;
                acc[i][1] += p.x * v0.y + p.y * v1.y + p.z * v2.y + p.w * v3.y;
                acc[i][2] += p.x * v0.z + p.y * v1.z + p.z * v2.z + p.w * v3.z;
                acc[i][3] += p.x * v0.w + p.y * v1.w + p.z * v2.w + p.w * v3.w;
            }
        }
    }

    // ---- epilogue: normalize + store ----
#pragma unroll
    for (int i = 0; i < 8; i++) {
        int r = (i < 4) ? (ty * 4 + i) : (60 + ty * 4 + i);
        float inv_l = 1.f / l[i];
        float4 o;
        o.x = acc[i][0] * inv_l;
        o.y = acc[i][1] * inv_l;
        o.z = acc[i][2] * inv_l;
        o.w = acc[i][3] * inv_l;
        *(float4*)&Ctx[base + (size_t)(q0 + r) * HID + tx * 4] = o;
    }
}

// ---------------------------------------------------------------------------
// LayerNorm: one block per row of 1024
// ---------------------------------------------------------------------------
__global__ __launch_bounds__(256)
void layernorm_kernel(const float* __restrict__ X, const float* __restrict__ gamma,
                      const float* __restrict__ beta, float* __restrict__ out)
{
    __shared__ float red[2][8];
    const int row = blockIdx.x;
    const int tid = threadIdx.x;
    const float* x = X + (size_t)row * HID;

    float4 v = *(const float4*)&x[tid * 4];
    float s  = v.x + v.y + v.z + v.w;
    float ss = v.x * v.x + v.y * v.y + v.z * v.z + v.w * v.w;
#pragma unroll
    for (int o = 16; o > 0; o >>= 1) {
        s  += __shfl_xor_sync(0xffffffffu, s, o);
        ss += __shfl_xor_sync(0xffffffffu, ss, o);
    }
    const int w = tid >> 5, l = tid & 31;
    if (l == 0) { red[0][w] = s; red[1][w] = ss; }
    __syncthreads();
    if (w == 0) {
        float s2  = (l < 8) ? red[0][l] : 0.f;
        float ss2 = (l < 8) ? red[1][l] : 0.f;
#pragma unroll
        for (int o = 4; o > 0; o >>= 1) {
            s2  += __shfl_xor_sync(0xffffffffu, s2, o);
            ss2 += __shfl_xor_sync(0xffffffffu, ss2, o);
        }
        if (l == 0) { red[0][0] = s2; red[1][0] = ss2; }
    }
    __syncthreads();

    const float mean = red[0][0] * (1.f / HID);
    const float var  = red[1][0] * (1.f / HID) - mean * mean;
    const float rstd = rsqrtf(var + 1e-5f);

    const int c = tid * 4;
    float4 gv = *(const float4*)&gamma[c];
    float4 bv = *(const float4*)&beta[c];
    float4 o;
    o.x = (v.x - mean) * rstd * gv.x + bv.x;
    o.y = (v.y - mean) * rstd * gv.y + bv.y;
    o.z = (v.z - mean) * rstd * gv.z + bv.z;
    o.w = (v.w - mean) * rstd * gv.w + bv.w;
    *(float4*)&out[(size_t)row * HID + c] = o;
}

// ---------------------------------------------------------------------------
// Launch
// ---------------------------------------------------------------------------
extern "C" void kernel_launch(void* const* d_in, const int* in_sizes, int n_in,
                              void* d_out, int out_size)
{
    const float* hidden = (const float*)d_in[0];
    const float* Wq = (const float*)d_in[1];
    const float* bq = (const float*)d_in[2];
    const float* Wk = (const float*)d_in[3];
    const float* bk = (const float*)d_in[4];
    const float* Wv = (const float*)d_in[5];
    const float* bv = (const float*)d_in[6];
    const float* Wo = (const float*)d_in[7];
    const float* bo = (const float*)d_in[8];
    const float* gamma = (const float*)d_in[9];
    const float* beta  = (const float*)d_in[10];
    float* out = (float*)d_out;

    float *q, *k, *v, *ctx, *x;
    cudaGetSymbolAddress((void**)&q,   g_Q);
    cudaGetSymbolAddress((void**)&k,   g_K);
    cudaGetSymbolAddress((void**)&v,   g_V);
    cudaGetSymbolAddress((void**)&ctx, g_CTX);
    cudaGetSymbolAddress((void**)&x,   g_X);

    dim3 gg(HID / BN, ROWS / BM);   // (8, 32)
    dim3 bb(256);

    sgemm_bias<<<gg, bb>>>(hidden, Wq, bq, nullptr, q, ROWS, HID, HID);
    sgemm_bias<<<gg, bb>>>(hidden, Wk, bk, nullptr, k, ROWS, HID, HID);
    sgemm_bias<<<gg, bb>>>(hidden, Wv, bv, nullptr, v, ROWS, HID, HID);

    cudaFuncSetAttribute(flash_attn, cudaFuncAttributeMaxDynamicSharedMemorySize,
                         ATT_SMEM_BYTES);
    flash_attn<<<dim3(SEQ / BQ, HEADS, BATCH), 256, ATT_SMEM_BYTES>>>(q, k, v, ctx);

    sgemm_bias<<<gg, bb>>>(ctx, Wo, bo, hidden, x, ROWS, HID, HID);

    layernorm_kernel<<<ROWS, 256>>>(x, gamma, beta, out);
}